// round 1
// baseline (speedup 1.0000x reference)
#include <cuda_runtime.h>
#include <cuda_bf16.h>

// Problem: text [SEQ=200, BATCH=4096] int32 token ids (row-major: text[s*BATCH+b]),
// w_weight [1, V=50000] f32, w_bias [1] f32.
// out[b] = sum_{unique tokens t in column b} w_weight[t] + bias.
//
// Strategy: one block per document. Load 200 tokens to smem, O(n^2) first-occurrence
// dedup (cheap: worst thread scans 199 smem words), gather weights (L2-resident
// 200KB table), block-reduce, add bias.

#define SEQ 200
#define BATCH 4096

__global__ __launch_bounds__(256, 8)
void MNB_24111946400019_kernel(const int* __restrict__ text,
                               const float* __restrict__ w,
                               const float* __restrict__ bias,
                               float* __restrict__ out)
{
    __shared__ int toks[SEQ];
    __shared__ float warp_sums[8];

    const int b   = blockIdx.x;
    const int tid = threadIdx.x;

    // Cooperative load of this document's tokens (strided gather; neighbors share sectors)
    if (tid < SEQ) {
        toks[tid] = text[tid * BATCH + b];
    }
    __syncthreads();

    // First-occurrence dedup + weight gather
    float v = 0.0f;
    if (tid < SEQ) {
        const int t = toks[tid];
        bool uniq = true;
        #pragma unroll 4
        for (int j = 0; j < tid; ++j) {
            if (toks[j] == t) { uniq = false; break; }
        }
        if (uniq) v = __ldg(&w[t]);
    }

    // Block reduction (8 warps)
    #pragma unroll
    for (int o = 16; o > 0; o >>= 1)
        v += __shfl_down_sync(0xffffffffu, v, o);
    if ((tid & 31) == 0) warp_sums[tid >> 5] = v;
    __syncthreads();

    if (tid < 32) {
        float s = (tid < 8) ? warp_sums[tid] : 0.0f;
        #pragma unroll
        for (int o = 4; o > 0; o >>= 1)
            s += __shfl_down_sync(0xffffffffu, s, o);
        if (tid == 0) out[b] = s + bias[0];
    }
}

extern "C" void kernel_launch(void* const* d_in, const int* in_sizes, int n_in,
                              void* d_out, int out_size)
{
    const int*   text = (const int*)d_in[0];
    const float* w    = (const float*)d_in[1];
    const float* bias = (const float*)d_in[2];
    float*       out  = (float*)d_out;

    MNB_24111946400019_kernel<<<BATCH, 256>>>(text, w, bias, out);
}

// round 2
// speedup vs baseline: 1.9458x; 1.9458x over previous
#include <cuda_runtime.h>
#include <cuda_bf16.h>

// Problem: text [SEQ=200, BATCH=4096] int32 (row-major text[s*BATCH+b]),
// w_weight [V=50000] f32, w_bias [1] f32.
// out[b] = sum_{unique tokens t in doc b} w[t] + bias.
//
// R2: O(n) smem hash-set dedup (512 slots, CAS insert + atomicMin owner)
// replaces the O(n^2) scan that made R1 ALU/issue-bound (alu=45%).
// Owner = min seq index => deterministic reduction order.

#define SEQ   200
#define BATCH 4096
#define HBITS 9
#define HSIZE (1 << HBITS)   // 512 slots, load factor 200/512

__global__ __launch_bounds__(256, 8)
void MNB_24111946400019_kernel(const int* __restrict__ text,
                               const float* __restrict__ w,
                               const float* __restrict__ bias,
                               float* __restrict__ out)
{
    __shared__ int   key[HSIZE];
    __shared__ int   owner[HSIZE];
    __shared__ float warp_sums[8];

    const int b   = blockIdx.x;
    const int tid = threadIdx.x;

    // Init hash table (512/256 = 2 slots per thread)
    #pragma unroll
    for (int i = tid; i < HSIZE; i += 256) {
        key[i]   = -1;
        owner[i] = 0x7fffffff;
    }

    // Kick off the token load early (overlaps with init of other warps)
    int t = 0;
    if (tid < SEQ) t = text[tid * BATCH + b];

    __syncthreads();

    // Phase A: insert into hash set, record min-tid owner per unique token
    int slot = -1;
    if (tid < SEQ) {
        unsigned h = ((unsigned)t * 2654435761u) >> (32 - HBITS);
        for (;;) {
            int old = atomicCAS(&key[h], -1, t);
            if (old == -1 || old == t) {
                atomicMin(&owner[h], tid);
                slot = (int)h;
                break;
            }
            h = (h + 1) & (HSIZE - 1);
        }
    }
    __syncthreads();

    // Phase B: deterministic owner contributes the weight
    float v = 0.0f;
    if (slot >= 0 && owner[slot] == tid) {
        v = __ldg(&w[t]);
    }

    // Block reduction (8 warps)
    #pragma unroll
    for (int o = 16; o > 0; o >>= 1)
        v += __shfl_down_sync(0xffffffffu, v, o);
    if ((tid & 31) == 0) warp_sums[tid >> 5] = v;
    __syncthreads();

    if (tid < 32) {
        float s = (tid < 8) ? warp_sums[tid] : 0.0f;
        #pragma unroll
        for (int o = 4; o > 0; o >>= 1)
            s += __shfl_down_sync(0xffffffffu, s, o);
        if (tid == 0) out[b] = s + bias[0];
    }
}

extern "C" void kernel_launch(void* const* d_in, const int* in_sizes, int n_in,
                              void* d_out, int out_size)
{
    const int*   text = (const int*)d_in[0];
    const float* w    = (const float*)d_in[1];
    const float* bias = (const float*)d_in[2];
    float*       out  = (float*)d_out;

    MNB_24111946400019_kernel<<<BATCH, 256>>>(text, w, bias, out);
}